// round 15
// baseline (speedup 1.0000x reference)
#include <cuda_runtime.h>
#include <cstdint>

// SpikingNeuronLayer — r15: FFMA2 v2 (no splat MOVs), bitwise-frozen numerics.
// Numerics contract (r12, rel_err=0.0 — DO NOT CHANGE):
//   p1 = fused ascending fp32 chain k in [0,512), fresh acc
//   p2 = fused ascending fp32 chain k in [512,1024), fresh acc
//   I  = fl( fl(p1+p2) + b )
//   scan: mem = fma(alpha, mem, I_t); s = mem>=1; mem *= (1-s)   [fused]
// r13 lesson: FFMA2 with per-kk register splats regressed (mov overhead /
// banking). v2 pairs along M so A pairs load directly from As (LDS.64x2 via
// one LDS.128), and B splat-pairs come from a DUPLICATED smem copy written
// once per tile — the inner loop has 6 LDS.128 + 32 FFMA2 and zero MOVs.

namespace {
constexpr int BATCH  = 64;
constexpr int TSTEPS = 512;
constexpr int INDIM  = 1024;
constexpr int HID    = 1024;
constexpr int M      = BATCH * TSTEPS;   // 32768
constexpr int KSPLIT = 512;              // Eigen gebp kc panel size (confirmed)
constexpr float ALPHA = 0.9512294245007140f;  // exp(-1/20) rounded to f32

constexpr int BM = 128, BN = 128, BK = 16;
}

// Scratch for the GEMM output I[M, HID] (134 MB). Static device global: no allocs.
__device__ float g_I[(size_t)M * HID];

#define FMA2(d, a, b, c) \
    asm("fma.rn.f32x2 %0, %1, %2, %3;" : "=l"(d) : "l"(a), "l"(b), "l"(c))
#define UNPACK2(lo, hi, src) \
    asm("mov.b64 {%0, %1}, %2;" : "=f"(lo), "=f"(hi) : "l"(src))

__global__ __launch_bounds__(256, 1)
void gemm_bias_kernel(const float* __restrict__ A,   // x  [M, INDIM]
                      const float* __restrict__ B,   // W  [HID, INDIM]
                      const float* __restrict__ bias)
{
    // As: normal K-major-by-row layout (i contiguous) -> A i-pairs are native.
    __shared__ float As[BK][BM + 4];
    // Bsd: duplicated B. Chunk c (j-pair {2c,2c+1}) row: for tcol t the 4 floats
    // at [c][t*4 .. t*4+3] are (b_{t,2c}, b_{t,2c}, b_{t,2c+1}, b_{t,2c+1}).
    // 16 tcols read 256B contiguous per chunk -> conflict-free LDS.128.
    __shared__ float Bsd[BK][4][64 + 4];

    const int bm  = blockIdx.y * BM;
    const int bn  = blockIdx.x * BN;
    const int tid = threadIdx.x;

    const int tcol = tid & 15;   // across N (8 outputs)
    const int trow = tid >> 4;   // across M (8 outputs = 4 i-pairs)

    const int lrow = tid >> 2;          // 0..63
    const int lcol = (tid & 3) << 2;    // 0,4,8,12

    // accP[q][j]: 64-bit pair = outputs (i=2q, j) and (i=2q+1, j).
    unsigned long long accA[4][8], accB[4][8];
#pragma unroll
    for (int q = 0; q < 4; q++)
#pragma unroll
        for (int j = 0; j < 8; j++) { accA[q][j] = 0ull; accB[q][j] = 0ull; }

    const float* Ap = A + (size_t)bm * INDIM;
    const float* Bp = B + (size_t)bn * INDIM;

    for (int k0 = 0; k0 < INDIM; k0 += BK) {
        float4 a0 = *(const float4*)(Ap + (size_t)lrow        * INDIM + k0 + lcol);
        float4 a1 = *(const float4*)(Ap + (size_t)(lrow + 64) * INDIM + k0 + lcol);
        float4 b0 = *(const float4*)(Bp + (size_t)lrow        * INDIM + k0 + lcol);
        float4 b1 = *(const float4*)(Bp + (size_t)(lrow + 64) * INDIM + k0 + lcol);

        As[lcol + 0][lrow] = a0.x; As[lcol + 1][lrow] = a0.y;
        As[lcol + 2][lrow] = a0.z; As[lcol + 3][lrow] = a0.w;
        As[lcol + 0][lrow + 64] = a1.x; As[lcol + 1][lrow + 64] = a1.y;
        As[lcol + 2][lrow + 64] = a1.z; As[lcol + 3][lrow + 64] = a1.w;

        // duplicated B writes: value at tile-col n, k-row kq goes to
        // Bsd[kq][(n&7)>>1][(n>>3)*4 + (n&1)*2 + {0,1}]
        {
            const float bv0[4] = {b0.x, b0.y, b0.z, b0.w};
            const float bv1[4] = {b1.x, b1.y, b1.z, b1.w};
            const int n0 = lrow, n1 = lrow + 64;
            const int c0 = (n0 & 7) >> 1, o0 = (n0 >> 3) * 4 + (n0 & 1) * 2;
            const int c1 = (n1 & 7) >> 1, o1 = (n1 >> 3) * 4 + (n1 & 1) * 2;
#pragma unroll
            for (int q = 0; q < 4; q++) {
                Bsd[lcol + q][c0][o0 + 0] = bv0[q];
                Bsd[lcol + q][c0][o0 + 1] = bv0[q];
                Bsd[lcol + q][c1][o1 + 0] = bv1[q];
                Bsd[lcol + q][c1][o1 + 1] = bv1[q];
            }
        }
        __syncthreads();

        const bool panel1 = (k0 < KSPLIT);   // uniform per tile
#pragma unroll
        for (int kk = 0; kk < BK; kk++) {
            // A i-pairs: two LDS.128, each = two 64-bit pairs (no MOVs)
            ulonglong2 a01 = *(const ulonglong2*)&As[kk][trow * 8];
            ulonglong2 a23 = *(const ulonglong2*)&As[kk][trow * 8 + 4];
            unsigned long long ap[4] = {a01.x, a01.y, a23.x, a23.y};

            // B splat-pairs: four LDS.128 from the duplicated copy
            ulonglong2 bc0 = *(const ulonglong2*)&Bsd[kk][0][tcol * 4];
            ulonglong2 bc1 = *(const ulonglong2*)&Bsd[kk][1][tcol * 4];
            ulonglong2 bc2 = *(const ulonglong2*)&Bsd[kk][2][tcol * 4];
            ulonglong2 bc3 = *(const ulonglong2*)&Bsd[kk][3][tcol * 4];
            unsigned long long bp[8] = {bc0.x, bc0.y, bc1.x, bc1.y,
                                        bc2.x, bc2.y, bc3.x, bc3.y};

            if (panel1) {
#pragma unroll
                for (int q = 0; q < 4; q++)
#pragma unroll
                    for (int j = 0; j < 8; j++)
                        FMA2(accA[q][j], ap[q], bp[j], accA[q][j]);
            } else {
#pragma unroll
                for (int q = 0; q < 4; q++)
#pragma unroll
                    for (int j = 0; j < 8; j++)
                        FMA2(accB[q][j], ap[q], bp[j], accB[q][j]);
            }
        }
        __syncthreads();
    }

    // epilogue: dot = fl(p1+p2); I = fl(dot + b)  — identical to r12
    float bj[8];
#pragma unroll
    for (int j = 0; j < 8; j++) bj[j] = bias[bn + tcol * 8 + j];

#pragma unroll
    for (int q = 0; q < 4; q++) {
        float p1lo[8], p1hi[8], p2lo[8], p2hi[8];
#pragma unroll
        for (int j = 0; j < 8; j++) {
            UNPACK2(p1lo[j], p1hi[j], accA[q][j]);
            UNPACK2(p2lo[j], p2hi[j], accB[q][j]);
        }
        const int row0 = bm + trow * 8 + 2 * q;
        float* out0 = g_I + (size_t)row0 * HID + bn + tcol * 8;
        float* out1 = out0 + HID;
#pragma unroll
        for (int j = 0; j < 8; j += 4) {
            float4 v0, v1;
            v0.x = __fadd_rn(__fadd_rn(p1lo[j + 0], p2lo[j + 0]), bj[j + 0]);
            v0.y = __fadd_rn(__fadd_rn(p1lo[j + 1], p2lo[j + 1]), bj[j + 1]);
            v0.z = __fadd_rn(__fadd_rn(p1lo[j + 2], p2lo[j + 2]), bj[j + 2]);
            v0.w = __fadd_rn(__fadd_rn(p1lo[j + 3], p2lo[j + 3]), bj[j + 3]);
            v1.x = __fadd_rn(__fadd_rn(p1hi[j + 0], p2hi[j + 0]), bj[j + 0]);
            v1.y = __fadd_rn(__fadd_rn(p1hi[j + 1], p2hi[j + 1]), bj[j + 1]);
            v1.z = __fadd_rn(__fadd_rn(p1hi[j + 2], p2hi[j + 2]), bj[j + 2]);
            v1.w = __fadd_rn(__fadd_rn(p1hi[j + 3], p2hi[j + 3]), bj[j + 3]);
            *(float4*)(out0 + j) = v0;
            *(float4*)(out1 + j) = v1;
        }
    }
}

__global__ __launch_bounds__(256)
void lif_scan_kernel(float* __restrict__ spikes,    // [BATCH, TSTEPS, HID]
                     float* __restrict__ mem_final) // [BATCH, HID]
{
    const int idx = blockIdx.x * blockDim.x + threadIdx.x;  // 0 .. BATCH*HID-1
    const int b = idx / HID;
    const int h = idx - b * HID;

    const float* ip = g_I    + (size_t)b * TSTEPS * HID + h;
    float*       sp = spikes + (size_t)b * TSTEPS * HID + h;

    // depth-8 register prefetch pipeline (r13, measured 62us). Frozen.
    constexpr int PF = 8;
    float buf[PF];
#pragma unroll
    for (int t = 0; t < PF; t++) buf[t] = __ldg(&ip[(size_t)t * HID]);

    float mem = 0.0f;
    for (int t0 = 0; t0 < TSTEPS; t0 += PF) {
#pragma unroll
        for (int u = 0; u < PF; u++) {
            const int t = t0 + u;
            const float cur = buf[u];
            if (t + PF < TSTEPS) buf[u] = __ldg(&ip[(size_t)(t + PF) * HID]);
            mem = __fmaf_rn(ALPHA, mem, cur);
            const float s = (mem >= 1.0f) ? 1.0f : 0.0f;
            sp[(size_t)t * HID] = s;
            mem = mem * (1.0f - s);   // exact: multiplies by 0.0 or 1.0
        }
    }
    mem_final[idx] = mem;
}

extern "C" void kernel_launch(void* const* d_in, const int* in_sizes, int n_in,
                              void* d_out, int out_size)
{
    (void)in_sizes; (void)n_in; (void)out_size;
    const float* x    = (const float*)d_in[0];
    const float* W    = (const float*)d_in[1];
    const float* bias = (const float*)d_in[2];

    float* out    = (float*)d_out;
    float* spikes = out;                              // [B,T,H]
    float* memf   = out + (size_t)M * HID;            // [B,H]

    dim3 grid(HID / BN, M / BM);   // (8, 256)
    gemm_bias_kernel<<<grid, 256>>>(x, W, bias);

    lif_scan_kernel<<<(BATCH * HID) / 256, 256>>>(spikes, memf);
}

// round 16
// speedup vs baseline: 1.1208x; 1.1208x over previous
#include <cuda_runtime.h>
#include <cstdint>

// SpikingNeuronLayer — r16: revert GEMM to r12 scalar (measured 1782us, at the
// fp32 FFMA issue roofline: 2.04GHz x 148SM x 64 FMA/cyc); FFMA2 family closed
// after two measured regressions (rt=3 banking + suspected demotion).
// Scan: PF=16 prefetch (4MB in flight) + streaming spike stores.
// Numerics contract (r12, rel_err=0.0 — DO NOT CHANGE):
//   p1 = fused ascending fp32 chain k in [0,512), fresh acc
//   p2 = fused ascending fp32 chain k in [512,1024), fresh acc
//   I  = fl( fl(p1+p2) + b )
//   scan: mem = fma(alpha, mem, I_t); s = mem>=1; mem *= (1-s)   [fused]

namespace {
constexpr int BATCH  = 64;
constexpr int TSTEPS = 512;
constexpr int INDIM  = 1024;
constexpr int HID    = 1024;
constexpr int M      = BATCH * TSTEPS;   // 32768
constexpr int KSPLIT = 512;              // Eigen gebp kc panel size (confirmed)
constexpr float ALPHA = 0.9512294245007140f;  // exp(-1/20) rounded to f32

constexpr int BM = 128, BN = 128, BK = 16;
}

// Scratch for the GEMM output I[M, HID] (134 MB). Static device global: no allocs.
__device__ float g_I[(size_t)M * HID];

__global__ __launch_bounds__(256, 1)
void gemm_bias_kernel(const float* __restrict__ A,   // x  [M, INDIM]
                      const float* __restrict__ B,   // W  [HID, INDIM]
                      const float* __restrict__ bias)
{
    __shared__ float As[BK][BM + 4];
    __shared__ float Bs[BK][BN + 4];

    const int bm  = blockIdx.y * BM;
    const int bn  = blockIdx.x * BN;
    const int tid = threadIdx.x;

    const int tcol = tid & 15;   // across N
    const int trow = tid >> 4;   // across M

    const int lrow = tid >> 2;          // 0..63
    const int lcol = (tid & 3) << 2;    // 0,4,8,12

    // Two accumulator sets: panel 1 (k<512) and panel 2 (k>=512).
    float acc1[8][8], acc2[8][8];
#pragma unroll
    for (int i = 0; i < 8; i++)
#pragma unroll
        for (int j = 0; j < 8; j++) { acc1[i][j] = 0.0f; acc2[i][j] = 0.0f; }

    const float* Ap = A + (size_t)bm * INDIM;
    const float* Bp = B + (size_t)bn * INDIM;

    for (int k0 = 0; k0 < INDIM; k0 += BK) {
        float4 a0 = *(const float4*)(Ap + (size_t)lrow        * INDIM + k0 + lcol);
        float4 a1 = *(const float4*)(Ap + (size_t)(lrow + 64) * INDIM + k0 + lcol);
        float4 b0 = *(const float4*)(Bp + (size_t)lrow        * INDIM + k0 + lcol);
        float4 b1 = *(const float4*)(Bp + (size_t)(lrow + 64) * INDIM + k0 + lcol);

        As[lcol + 0][lrow] = a0.x; As[lcol + 1][lrow] = a0.y;
        As[lcol + 2][lrow] = a0.z; As[lcol + 3][lrow] = a0.w;
        As[lcol + 0][lrow + 64] = a1.x; As[lcol + 1][lrow + 64] = a1.y;
        As[lcol + 2][lrow + 64] = a1.z; As[lcol + 3][lrow + 64] = a1.w;

        Bs[lcol + 0][lrow] = b0.x; Bs[lcol + 1][lrow] = b0.y;
        Bs[lcol + 2][lrow] = b0.z; Bs[lcol + 3][lrow] = b0.w;
        Bs[lcol + 0][lrow + 64] = b1.x; Bs[lcol + 1][lrow + 64] = b1.y;
        Bs[lcol + 2][lrow + 64] = b1.z; Bs[lcol + 3][lrow + 64] = b1.w;

        __syncthreads();

        const bool panel1 = (k0 < KSPLIT);
#pragma unroll
        for (int kk = 0; kk < BK; kk++) {
            float ar[8], br[8];
            *(float4*)&ar[0] = *(const float4*)&As[kk][trow * 8];
            *(float4*)&ar[4] = *(const float4*)&As[kk][trow * 8 + 4];
            *(float4*)&br[0] = *(const float4*)&Bs[kk][tcol * 8];
            *(float4*)&br[4] = *(const float4*)&Bs[kk][tcol * 8 + 4];
            if (panel1) {
#pragma unroll
                for (int i = 0; i < 8; i++)
#pragma unroll
                    for (int j = 0; j < 8; j++)
                        acc1[i][j] = __fmaf_rn(ar[i], br[j], acc1[i][j]);
            } else {
#pragma unroll
                for (int i = 0; i < 8; i++)
#pragma unroll
                    for (int j = 0; j < 8; j++)
                        acc2[i][j] = __fmaf_rn(ar[i], br[j], acc2[i][j]);
            }
        }
        __syncthreads();
    }

    // combine panels (one rounding), then one bias add, write I
    float bj[8];
#pragma unroll
    for (int j = 0; j < 8; j++) bj[j] = bias[bn + tcol * 8 + j];

#pragma unroll
    for (int i = 0; i < 8; i++) {
        const int row = bm + trow * 8 + i;
        float* out = g_I + (size_t)row * HID + bn + tcol * 8;
#pragma unroll
        for (int j = 0; j < 8; j += 4) {
            float4 v;
            v.x = __fadd_rn(__fadd_rn(acc1[i][j + 0], acc2[i][j + 0]), bj[j + 0]);
            v.y = __fadd_rn(__fadd_rn(acc1[i][j + 1], acc2[i][j + 1]), bj[j + 1]);
            v.z = __fadd_rn(__fadd_rn(acc1[i][j + 2], acc2[i][j + 2]), bj[j + 2]);
            v.w = __fadd_rn(__fadd_rn(acc1[i][j + 3], acc2[i][j + 3]), bj[j + 3]);
            *(float4*)(out + j) = v;
        }
    }
}

__global__ __launch_bounds__(256)
void lif_scan_kernel(float* __restrict__ spikes,    // [BATCH, TSTEPS, HID]
                     float* __restrict__ mem_final) // [BATCH, HID]
{
    const int idx = blockIdx.x * blockDim.x + threadIdx.x;  // 0 .. BATCH*HID-1
    const int b = idx / HID;
    const int h = idx - b * HID;

    const float* ip = g_I    + (size_t)b * TSTEPS * HID + h;
    float*       sp = spikes + (size_t)b * TSTEPS * HID + h;

    // depth-16 register prefetch pipeline: 4MB in flight chip-wide.
    // Arithmetic chain untouched (bitwise identical to r12).
    constexpr int PF = 16;
    float buf[PF];
#pragma unroll
    for (int t = 0; t < PF; t++) buf[t] = __ldg(&ip[(size_t)t * HID]);

    float mem = 0.0f;
    for (int t0 = 0; t0 < TSTEPS; t0 += PF) {
#pragma unroll
        for (int u = 0; u < PF; u++) {
            const int t = t0 + u;
            const float cur = buf[u];
            if (t + PF < TSTEPS) buf[u] = __ldg(&ip[(size_t)(t + PF) * HID]);
            mem = __fmaf_rn(ALPHA, mem, cur);
            const float s = (mem >= 1.0f) ? 1.0f : 0.0f;
            __stcg(&sp[(size_t)t * HID], s);   // streaming store: spikes never re-read
            mem = mem * (1.0f - s);            // exact: multiplies by 0.0 or 1.0
        }
    }
    mem_final[idx] = mem;
}

extern "C" void kernel_launch(void* const* d_in, const int* in_sizes, int n_in,
                              void* d_out, int out_size)
{
    (void)in_sizes; (void)n_in; (void)out_size;
    const float* x    = (const float*)d_in[0];
    const float* W    = (const float*)d_in[1];
    const float* bias = (const float*)d_in[2];

    float* out    = (float*)d_out;
    float* spikes = out;                              // [B,T,H]
    float* memf   = out + (size_t)M * HID;            // [B,H]

    dim3 grid(HID / BN, M / BM);   // (8, 256)
    gemm_bias_kernel<<<grid, 256>>>(x, W, bias);

    lif_scan_kernel<<<(BATCH * HID) / 256, 256>>>(spikes, memf);
}